// round 15
// baseline (speedup 1.0000x reference)
#include <cuda_runtime.h>
#include <cuda_bf16.h>
#include <cstdint>

#define LSEQ 8192
#define FIN  1024
#define CDIM 256
#define C3   768
#define NH   8
#define DH   32
#define KS   63

__device__ float g_xp[LSEQ * FIN];     // permuted+rounded x (32 MB)
__device__ float g_y[LSEQ * CDIM];     // permuted+rounded y
__device__ float g_qkv[LSEQ * C3];     // natural fp32
__device__ float g_att[LSEQ * CDIM];   // permuted+rounded att

// Fragment-permuted tf32-rounded weights (round-12 layout)
__device__ float g_Wp_p[(FIN / 8) * (CDIM / 8) * 64];
__device__ float g_Wq_p[(CDIM / 8) * (C3 / 8) * 64];
__device__ float g_Wo_p[(CDIM / 8) * (CDIM / 8) * 64];

// ---------------------------------------------------------------------------
// helpers
// ---------------------------------------------------------------------------
__device__ __forceinline__ void cp16(void* smem, const void* g) {
    uint32_t s = (uint32_t)__cvta_generic_to_shared(smem);
    asm volatile("cp.async.cg.shared.global [%0], [%1], 16;\n" :: "r"(s), "l"(g));
}
__device__ __forceinline__ void cp_commit() {
    asm volatile("cp.async.commit_group;\n");
}
__device__ __forceinline__ void mma_tf32(float* d, const uint32_t* a, const uint32_t* b) {
    asm volatile(
        "mma.sync.aligned.m16n8k8.row.col.f32.tf32.tf32.f32 "
        "{%0,%1,%2,%3}, {%4,%5,%6,%7}, {%8,%9}, {%0,%1,%2,%3};\n"
        : "+f"(d[0]), "+f"(d[1]), "+f"(d[2]), "+f"(d[3])
        : "r"(a[0]), "r"(a[1]), "r"(a[2]), "r"(a[3]), "r"(b[0]), "r"(b[1]));
}
__device__ __forceinline__ uint32_t cvt_rna_tf32(float x) {
    uint32_t r;
    asm("cvt.rna.tf32.f32 %0, %1;" : "=r"(r) : "f"(x));
    return r;
}
__device__ __forceinline__ float round_tf32(float x) {
    return __uint_as_float(cvt_rna_tf32(x));
}
// k-chunk permutation: j -> ((j&3)<<1)|(j>>2), applied to low 3 bits
__device__ __forceinline__ int permc(int k) {
    return (k & ~7) | (((k & 3) << 1) | ((k >> 2) & 1));
}

// ---------------------------------------------------------------------------
// Prep: x -> xp (tf32-rounded, k-permuted)
// ---------------------------------------------------------------------------
__global__ void prep_x_kernel(const float* __restrict__ X,
                              float* __restrict__ Xp, int total, int K)
{
    int idx = blockIdx.x * blockDim.x + threadIdx.x;
    if (idx >= total) return;
    int row = idx / K;
    int k = idx % K;
    Xp[(size_t)row * K + permc(k)] = round_tf32(X[idx]);
}

// ---------------------------------------------------------------------------
// Prep: W[K][N] -> Bp fragment-permuted, tf32-RNE rounded (round-12 layout)
// ---------------------------------------------------------------------------
__global__ void prep_weights_kernel(const float* __restrict__ W,
                                    float* __restrict__ Bp, int K, int N)
{
    int idx = blockIdx.x * blockDim.x + threadIdx.x;
    int total = (K / 8) * (N / 8) * 64;
    if (idx >= total) return;
    int slot = idx & 1;
    int lane = (idx >> 1) & 31;
    int blk  = idx >> 6;
    int n8   = blk % (N / 8);
    int k8   = blk / (N / 8);
    int kk = k8 * 8 + slot * 4 + (lane & 3);
    int nn = n8 * 8 + (lane >> 2);
    Bp[idx] = round_tf32(W[(size_t)kk * N + nn]);
}

// ---------------------------------------------------------------------------
// TF32 GEMM v3: BM=128 BN=64 BK=16, 2-stage. A k-permuted (LDS.64 frags),
// B fragment-permuted (LDS.64). PERM_OUT: store C k-permuted + rounded.
// ---------------------------------------------------------------------------
#define ASTRIDE 20

template<bool PERM_OUT>
__global__ __launch_bounds__(256) void gemm_tf32_kernel(
    const float* __restrict__ A, const float* __restrict__ Bp,
    const float* __restrict__ bias, float* __restrict__ C,
    int M, int N, int K)
{
    __shared__ float As[2][128 * ASTRIDE];
    __shared__ float Bs[2][1024];

    const int bm = blockIdx.y * 128;
    const int bn = blockIdx.x * 64;
    const int tid = threadIdx.x;
    const int wid = tid >> 5;
    const int lane = tid & 31;
    const int warp_m = wid & 3;
    const int warp_n = wid >> 2;
    const int r = lane >> 2;
    const int c = lane & 3;

    const int arow0 = tid >> 2;
    const int ac4   = (tid & 3) * 4;
    const int bk8l  = tid >> 7;
    const int bn8l  = (tid >> 4) & 7;
    const int bpart = tid & 15;
    const int n8cnt = N >> 3;

    float acc[2][4][4];
    #pragma unroll
    for (int i = 0; i < 2; i++)
        #pragma unroll
        for (int j = 0; j < 4; j++)
            #pragma unroll
            for (int e = 0; e < 4; e++) acc[i][j][e] = 0.f;

    const int T = K >> 4;

    auto stage = [&](int kt, int s) {
        const int k0 = kt << 4;
        cp16(&As[s][arow0 * ASTRIDE + ac4], &A[(size_t)(bm + arow0) * K + k0 + ac4]);
        cp16(&As[s][(arow0 + 64) * ASTRIDE + ac4], &A[(size_t)(bm + arow0 + 64) * K + k0 + ac4]);
        cp16(&Bs[s][(bk8l * 8 + bn8l) * 64 + bpart * 4],
             &Bp[(size_t)(((k0 >> 3) + bk8l) * n8cnt + (bn >> 3) + bn8l) * 64 + bpart * 4]);
        cp_commit();
    };

    stage(0, 0);

    for (int kt = 0; kt < T; kt++) {
        const int buf = kt & 1;
        if (kt + 1 < T) {
            stage(kt + 1, buf ^ 1);
            asm volatile("cp.async.wait_group 1;\n");
        } else {
            asm volatile("cp.async.wait_group 0;\n");
        }
        __syncthreads();

        const float* as = As[buf];
        const float* bs = Bs[buf];
        #pragma unroll
        for (int ks = 0; ks < 16; ks += 8) {
            uint32_t af[2][4], bf[4][2];
            #pragma unroll
            for (int mi = 0; mi < 2; mi++) {
                int m0 = warp_m * 32 + mi * 16;
                // permuted A: (a0,a2) and (a1,a3) are contiguous pairs
                float2 pA = *(const float2*)&as[(m0 + r)     * ASTRIDE + ks + 2 * c];
                float2 pB = *(const float2*)&as[(m0 + r + 8) * ASTRIDE + ks + 2 * c];
                af[mi][0] = __float_as_uint(pA.x);
                af[mi][1] = __float_as_uint(pB.x);
                af[mi][2] = __float_as_uint(pA.y);
                af[mi][3] = __float_as_uint(pB.y);
            }
            const int k8l = ks >> 3;
            #pragma unroll
            for (int nj = 0; nj < 4; nj++) {
                const float2 bb = *(const float2*)&bs[(k8l * 8 + warp_n * 4 + nj) * 64 + lane * 2];
                bf[nj][0] = __float_as_uint(bb.x);
                bf[nj][1] = __float_as_uint(bb.y);
            }
            #pragma unroll
            for (int mi = 0; mi < 2; mi++)
                #pragma unroll
                for (int nj = 0; nj < 4; nj++)
                    mma_tf32(acc[mi][nj], af[mi], bf[nj]);
        }
        __syncthreads();
    }

    #pragma unroll
    for (int mi = 0; mi < 2; mi++) {
        #pragma unroll
        for (int nj = 0; nj < 4; nj++) {
            int row = bm + warp_m * 32 + mi * 16 + r;
            int col = bn + warp_n * 32 + nj * 8 + c * 2;
            float2 bb = *(const float2*)&bias[col];
            float v00 = acc[mi][nj][0] + bb.x;
            float v01 = acc[mi][nj][1] + bb.y;
            float v10 = acc[mi][nj][2] + bb.x;
            float v11 = acc[mi][nj][3] + bb.y;
            if (PERM_OUT) {
                int p0 = permc(col);
                int p1 = permc(col + 1);
                C[(size_t)row * N + p0]       = round_tf32(v00);
                C[(size_t)row * N + p1]       = round_tf32(v01);
                C[(size_t)(row + 8) * N + p0] = round_tf32(v10);
                C[(size_t)(row + 8) * N + p1] = round_tf32(v11);
            } else {
                float2 o0 = make_float2(v00, v01);
                float2 o1 = make_float2(v10, v11);
                *(float2*)&C[(size_t)row * N + col] = o0;
                *(float2*)&C[(size_t)(row + 8) * N + col] = o1;
            }
        }
    }
}

// ---------------------------------------------------------------------------
// NATTEN-1D v3 (round-14): transposed-K outer product. att stored k-permuted
// + tf32-rounded for GEMM3.
// ---------------------------------------------------------------------------
#define TQ 64
#define KV 126
#define RS 36
#define KTS 137
#define PTS 12
#define PTROWS 72

__device__ __forceinline__ int win_start(int l) {
    int s = l - 31;
    if (s < 0) s = 0;
    if (s > LSEQ - KS) s = LSEQ - KS;
    return s;
}

__global__ __launch_bounds__(256) void natten_kernel(
    const float* __restrict__ qkv, float* __restrict__ out)
{
    extern __shared__ float sm[];
    float* Kt = sm;                       // 32 * 137
    float* Vs = Kt + 32 * KTS;            // 127 * 36
    float* Qs = Vs + 127 * RS;            // 64 * 36
    float* Pt = Qs + TQ * RS;             // 8 * 72 * 12

    const int t0 = blockIdx.x * TQ;
    const int h = blockIdx.y;
    const int tid = threadIdx.x;
    const int w = tid >> 5;
    const int lane = tid & 31;

    int base = t0 - 31;
    if (base < 0) base = 0;
    if (base > LSEQ - KV) base = LSEQ - KV;

    const float scale = 0.17677669529663687f;

    for (int idx = tid; idx < KV * 8; idx += 256) {
        int row = idx >> 3;
        int d4 = (idx & 7) * 4;
        size_t g = (size_t)(base + row) * C3 + CDIM + h * DH + d4;
        float4 kv = *(const float4*)&qkv[g];
        Kt[(d4 + 0) * KTS + row] = kv.x;
        Kt[(d4 + 1) * KTS + row] = kv.y;
        Kt[(d4 + 2) * KTS + row] = kv.z;
        Kt[(d4 + 3) * KTS + row] = kv.w;
        *(float4*)&Vs[row * RS + d4] = *(const float4*)&qkv[g + CDIM];
    }
    for (int idx = tid; idx < 32 * 11; idx += 256) {
        int d = idx & 31;
        int rr = 126 + (idx >> 5);
        Kt[d * KTS + rr] = 0.f;
    }
    if (tid < 32) Vs[126 * RS + tid] = 0.f;
    for (int idx = tid; idx < TQ * 8; idx += 256) {
        int row = idx >> 3;
        int d4 = (idx & 7) * 4;
        float4 q = *(const float4*)&qkv[(size_t)(t0 + row) * C3 + h * DH + d4];
        q.x *= scale; q.y *= scale; q.z *= scale; q.w *= scale;
        *(float4*)&Qs[row * RS + d4] = q;
    }
    __syncthreads();

    const int l0 = t0 + w * 8;
    const int ws0 = win_start(l0) - base;
    const int off7 = win_start(l0 + 7) - base - ws0;
    float* Ptw = Pt + w * PTROWS * PTS;
    const bool lk7 = (lane < 7);

    float s0[8], s1[8], s2[8];
    #pragma unroll
    for (int q = 0; q < 8; q++) { s0[q] = 0.f; s1[q] = 0.f; s2[q] = 0.f; }

    const float* qsw = &Qs[(w * 8) * RS];
    #pragma unroll 4
    for (int d = 0; d < 32; d++) {
        const float* ktd = &Kt[d * KTS + ws0 + lane];
        float k0 = ktd[0];
        float k1 = ktd[32];
        float k2 = lk7 ? ktd[64] : 0.f;
        #pragma unroll
        for (int q = 0; q < 8; q++) {
            float qd = qsw[q * RS + d];
            s0[q] = fmaf(qd, k0, s0[q]);
            s1[q] = fmaf(qd, k1, s1[q]);
            s2[q] = fmaf(qd, k2, s2[q]);
        }
    }

    #pragma unroll 1
    for (int q = 0; q < 8; q++) {
        const int off = win_start(l0 + q) - base - ws0;
        const bool v0 = (lane >= off);
        const bool v1 = (lane <= off + 30);
        const bool v2 = (lane + 2 <= off);
        float a0 = v0 ? s0[q] : -1e30f;
        float a1 = v1 ? s1[q] : -1e30f;
        float a2 = v2 ? s2[q] : -1e30f;
        float m = fmaxf(fmaxf(a0, a1), a2);
        #pragma unroll
        for (int o = 16; o > 0; o >>= 1)
            m = fmaxf(m, __shfl_xor_sync(0xffffffffu, m, o));
        float e0 = v0 ? __expf(s0[q] - m) : 0.f;
        float e1 = v1 ? __expf(s1[q] - m) : 0.f;
        float e2 = v2 ? __expf(s2[q] - m) : 0.f;
        float sum = e0 + e1 + e2;
        #pragma unroll
        for (int o = 16; o > 0; o >>= 1)
            sum += __shfl_xor_sync(0xffffffffu, sum, o);
        float inv = __frcp_rn(sum);
        Ptw[lane * PTS + q]        = e0 * inv;
        Ptw[(lane + 32) * PTS + q] = e1 * inv;
        if (lk7) Ptw[(lane + 64) * PTS + q] = e2 * inv;
    }
    __syncwarp();

    const int nU = off7 + 64;
    float acc[8];
    #pragma unroll
    for (int q = 0; q < 8; q++) acc[q] = 0.f;

    const float* vb = &Vs[ws0 * RS + lane];
    #pragma unroll 4
    for (int jj = 0; jj < nU; jj++) {
        float v = vb[jj * RS];
        float4 pa = *(const float4*)&Ptw[jj * PTS];
        float4 pb = *(const float4*)&Ptw[jj * PTS + 4];
        acc[0] = fmaf(pa.x, v, acc[0]);
        acc[1] = fmaf(pa.y, v, acc[1]);
        acc[2] = fmaf(pa.z, v, acc[2]);
        acc[3] = fmaf(pa.w, v, acc[3]);
        acc[4] = fmaf(pb.x, v, acc[4]);
        acc[5] = fmaf(pb.y, v, acc[5]);
        acc[6] = fmaf(pb.z, v, acc[6]);
        acc[7] = fmaf(pb.w, v, acc[7]);
    }

    // store k-permuted + rounded (GEMM3 A layout)
    const int plane = (lane & ~7) | (((lane & 3) << 1) | ((lane >> 2) & 1));
    #pragma unroll
    for (int q = 0; q < 8; q++)
        out[(size_t)(l0 + q) * CDIM + h * DH + plane] = round_tf32(acc[q]);
}

// ---------------------------------------------------------------------------
extern "C" void kernel_launch(void* const* d_in, const int* in_sizes, int n_in,
                              void* d_out, int out_size)
{
    const float* x    = (const float*)d_in[0];
    const float* Wp   = (const float*)d_in[1];
    const float* bp   = (const float*)d_in[2];
    const float* Wqkv = (const float*)d_in[3];
    const float* bqkv = (const float*)d_in[4];
    const float* Wo   = (const float*)d_in[5];
    const float* bo   = (const float*)d_in[6];
    float* out = (float*)d_out;

    float *p_xp, *p_y, *p_qkv, *p_att, *wpp, *wqp, *wop;
    cudaGetSymbolAddress((void**)&p_xp,  g_xp);
    cudaGetSymbolAddress((void**)&p_y,   g_y);
    cudaGetSymbolAddress((void**)&p_qkv, g_qkv);
    cudaGetSymbolAddress((void**)&p_att, g_att);
    cudaGetSymbolAddress((void**)&wpp, g_Wp_p);
    cudaGetSymbolAddress((void**)&wqp, g_Wq_p);
    cudaGetSymbolAddress((void**)&wop, g_Wo_p);

    const int natten_smem = (32 * KTS + 127 * RS + TQ * RS + 8 * PTROWS * PTS) * 4;
    static bool attr_set = false;
    if (!attr_set) {
        cudaFuncSetAttribute(natten_kernel,
                             cudaFuncAttributeMaxDynamicSharedMemorySize, natten_smem);
        attr_set = true;
    }

    prep_x_kernel<<<(LSEQ * FIN + 255) / 256, 256>>>(x, p_xp, LSEQ * FIN, FIN);
    prep_weights_kernel<<<(FIN * CDIM + 255) / 256, 256>>>(Wp, wpp, FIN, CDIM);
    prep_weights_kernel<<<(CDIM * C3 + 255) / 256, 256>>>(Wqkv, wqp, CDIM, C3);
    prep_weights_kernel<<<(CDIM * CDIM + 255) / 256, 256>>>(Wo, wop, CDIM, CDIM);

    // y = x @ Wp + bp : A = xp (perm), out y perm+rounded
    gemm_tf32_kernel<true><<<dim3(CDIM / 64, LSEQ / 128), 256>>>(
        p_xp, wpp, bp, p_y, LSEQ, CDIM, FIN);

    // qkv = y @ Wqkv + bqkv : A = y (perm), out natural fp32
    gemm_tf32_kernel<false><<<dim3(C3 / 64, LSEQ / 128), 256>>>(
        p_y, wqp, bqkv, p_qkv, LSEQ, C3, CDIM);

    natten_kernel<<<dim3(LSEQ / TQ, NH), 256, natten_smem>>>(p_qkv, p_att);

    // out = att @ Wo + bo : A = att (perm), out natural fp32
    gemm_tf32_kernel<false><<<dim3(CDIM / 64, LSEQ / 128), 256>>>(
        p_att, wop, bo, out, LSEQ, CDIM, CDIM);
}

// round 16
// speedup vs baseline: 1.2563x; 1.2563x over previous
#include <cuda_runtime.h>
#include <cuda_bf16.h>
#include <cstdint>

#define LSEQ 8192
#define FIN  1024
#define CDIM 256
#define C3   768
#define NH   8
#define DH   32
#define KS   63

__device__ float g_y[LSEQ * CDIM];     // k-permuted + rounded (GEMM2 A)
__device__ float g_qkv[LSEQ * C3];     // natural fp32
__device__ float g_att[LSEQ * CDIM];   // k-permuted + rounded (GEMM3 A)

// Fragment-permuted tf32-rounded weights (round-12 layout)
__device__ float g_Wp_p[(FIN / 8) * (CDIM / 8) * 64];
__device__ float g_Wq_p[(CDIM / 8) * (C3 / 8) * 64];
__device__ float g_Wo_p[(CDIM / 8) * (CDIM / 8) * 64];

// ---------------------------------------------------------------------------
// helpers
// ---------------------------------------------------------------------------
__device__ __forceinline__ void cp16(void* smem, const void* g) {
    uint32_t s = (uint32_t)__cvta_generic_to_shared(smem);
    asm volatile("cp.async.cg.shared.global [%0], [%1], 16;\n" :: "r"(s), "l"(g));
}
__device__ __forceinline__ void cp_commit() {
    asm volatile("cp.async.commit_group;\n");
}
__device__ __forceinline__ void mma_tf32(float* d, const uint32_t* a, const uint32_t* b) {
    asm volatile(
        "mma.sync.aligned.m16n8k8.row.col.f32.tf32.tf32.f32 "
        "{%0,%1,%2,%3}, {%4,%5,%6,%7}, {%8,%9}, {%0,%1,%2,%3};\n"
        : "+f"(d[0]), "+f"(d[1]), "+f"(d[2]), "+f"(d[3])
        : "r"(a[0]), "r"(a[1]), "r"(a[2]), "r"(a[3]), "r"(b[0]), "r"(b[1]));
}
__device__ __forceinline__ uint32_t cvt_rna_tf32(float x) {
    uint32_t r;
    asm("cvt.rna.tf32.f32 %0, %1;" : "=r"(r) : "f"(x));
    return r;
}
__device__ __forceinline__ float round_tf32(float x) {
    return __uint_as_float(cvt_rna_tf32(x));
}
// k-chunk permutation (low 3 bits): logical j -> physical ((j&3)<<1)|(j>>2)
__device__ __forceinline__ int permc(int k) {
    return (k & ~7) | (((k & 3) << 1) | ((k >> 2) & 1));
}

// ---------------------------------------------------------------------------
// Prep: W[K][N] -> Bp fragment-permuted, tf32-RNE rounded (round-12 layout)
// ---------------------------------------------------------------------------
__global__ void prep_weights_kernel(const float* __restrict__ W,
                                    float* __restrict__ Bp, int K, int N)
{
    int idx = blockIdx.x * blockDim.x + threadIdx.x;
    int total = (K / 8) * (N / 8) * 64;
    if (idx >= total) return;
    int slot = idx & 1;
    int lane = (idx >> 1) & 31;
    int blk  = idx >> 6;
    int n8   = blk % (N / 8);
    int k8   = blk / (N / 8);
    int kk = k8 * 8 + slot * 4 + (lane & 3);
    int nn = n8 * 8 + (lane >> 2);
    Bp[idx] = round_tf32(W[(size_t)kk * N + nn]);
}

// ---------------------------------------------------------------------------
// TF32 GEMM: BM=128 BN=64 BK=16, 2-stage, B fragment-permuted.
// PERM_A: A is k-permuted in gmem -> paired LDS.64 fragment loads, no CVT.
//         else: natural A, scalar LDS + inline cvt.rna (GEMM1).
// PERM_OUT: store C k-permuted + tf32-rounded (feeds a PERM_A GEMM).
// ASTRIDE=24: conflict-free for both A-load patterns.
// ---------------------------------------------------------------------------
#define ASTRIDE 24

template<bool PERM_A, bool PERM_OUT>
__global__ __launch_bounds__(256) void gemm_tf32_kernel(
    const float* __restrict__ A, const float* __restrict__ Bp,
    const float* __restrict__ bias, float* __restrict__ C,
    int M, int N, int K)
{
    __shared__ float As[2][128 * ASTRIDE];
    __shared__ float Bs[2][1024];

    const int bm = blockIdx.y * 128;
    const int bn = blockIdx.x * 64;
    const int tid = threadIdx.x;
    const int wid = tid >> 5;
    const int lane = tid & 31;
    const int warp_m = wid & 3;
    const int warp_n = wid >> 2;
    const int r = lane >> 2;
    const int c = lane & 3;

    const int arow0 = tid >> 2;
    const int ac4   = (tid & 3) * 4;
    const int bk8l  = tid >> 7;
    const int bn8l  = (tid >> 4) & 7;
    const int bpart = tid & 15;
    const int n8cnt = N >> 3;

    float acc[2][4][4];
    #pragma unroll
    for (int i = 0; i < 2; i++)
        #pragma unroll
        for (int j = 0; j < 4; j++)
            #pragma unroll
            for (int e = 0; e < 4; e++) acc[i][j][e] = 0.f;

    const int T = K >> 4;

    auto stage = [&](int kt, int s) {
        const int k0 = kt << 4;
        cp16(&As[s][arow0 * ASTRIDE + ac4], &A[(size_t)(bm + arow0) * K + k0 + ac4]);
        cp16(&As[s][(arow0 + 64) * ASTRIDE + ac4], &A[(size_t)(bm + arow0 + 64) * K + k0 + ac4]);
        cp16(&Bs[s][(bk8l * 8 + bn8l) * 64 + bpart * 4],
             &Bp[(size_t)(((k0 >> 3) + bk8l) * n8cnt + (bn >> 3) + bn8l) * 64 + bpart * 4]);
        cp_commit();
    };

    stage(0, 0);

    for (int kt = 0; kt < T; kt++) {
        const int buf = kt & 1;
        if (kt + 1 < T) {
            stage(kt + 1, buf ^ 1);
            asm volatile("cp.async.wait_group 1;\n");
        } else {
            asm volatile("cp.async.wait_group 0;\n");
        }
        __syncthreads();

        const float* as = As[buf];
        const float* bs = Bs[buf];
        #pragma unroll
        for (int ks = 0; ks < 16; ks += 8) {
            uint32_t af[2][4], bf[4][2];
            #pragma unroll
            for (int mi = 0; mi < 2; mi++) {
                int m0 = warp_m * 32 + mi * 16;
                if (PERM_A) {
                    float2 pA = *(const float2*)&as[(m0 + r)     * ASTRIDE + ks + 2 * c];
                    float2 pB = *(const float2*)&as[(m0 + r + 8) * ASTRIDE + ks + 2 * c];
                    af[mi][0] = __float_as_uint(pA.x);
                    af[mi][1] = __float_as_uint(pB.x);
                    af[mi][2] = __float_as_uint(pA.y);
                    af[mi][3] = __float_as_uint(pB.y);
                } else {
                    af[mi][0] = cvt_rna_tf32(as[(m0 + r)     * ASTRIDE + ks + c]);
                    af[mi][1] = cvt_rna_tf32(as[(m0 + r + 8) * ASTRIDE + ks + c]);
                    af[mi][2] = cvt_rna_tf32(as[(m0 + r)     * ASTRIDE + ks + c + 4]);
                    af[mi][3] = cvt_rna_tf32(as[(m0 + r + 8) * ASTRIDE + ks + c + 4]);
                }
            }
            const int k8l = ks >> 3;
            #pragma unroll
            for (int nj = 0; nj < 4; nj++) {
                const float2 bb = *(const float2*)&bs[(k8l * 8 + warp_n * 4 + nj) * 64 + lane * 2];
                bf[nj][0] = __float_as_uint(bb.x);
                bf[nj][1] = __float_as_uint(bb.y);
            }
            #pragma unroll
            for (int mi = 0; mi < 2; mi++)
                #pragma unroll
                for (int nj = 0; nj < 4; nj++)
                    mma_tf32(acc[mi][nj], af[mi], bf[nj]);
        }
        __syncthreads();
    }

    #pragma unroll
    for (int mi = 0; mi < 2; mi++) {
        #pragma unroll
        for (int nj = 0; nj < 4; nj++) {
            int row = bm + warp_m * 32 + mi * 16 + r;
            int col = bn + warp_n * 32 + nj * 8 + c * 2;
            float2 bb = *(const float2*)&bias[col];
            float v00 = acc[mi][nj][0] + bb.x;
            float v01 = acc[mi][nj][1] + bb.y;
            float v10 = acc[mi][nj][2] + bb.x;
            float v11 = acc[mi][nj][3] + bb.y;
            if (PERM_OUT) {
                int p0 = permc(col);
                int p1 = permc(col + 1);
                C[(size_t)row * N + p0]       = round_tf32(v00);
                C[(size_t)row * N + p1]       = round_tf32(v01);
                C[(size_t)(row + 8) * N + p0] = round_tf32(v10);
                C[(size_t)(row + 8) * N + p1] = round_tf32(v11);
            } else {
                *(float2*)&C[(size_t)row * N + col]       = make_float2(v00, v01);
                *(float2*)&C[(size_t)(row + 8) * N + col] = make_float2(v10, v11);
            }
        }
    }
}

// ---------------------------------------------------------------------------
// NATTEN-1D v3 (round-14): transposed-K outer product.
// att stored k-permuted + tf32-rounded (GEMM3 PERM_A layout).
// ---------------------------------------------------------------------------
#define TQ 64
#define KV 126
#define RS 36
#define KTS 137
#define PTS 12
#define PTROWS 72

__device__ __forceinline__ int win_start(int l) {
    int s = l - 31;
    if (s < 0) s = 0;
    if (s > LSEQ - KS) s = LSEQ - KS;
    return s;
}

__global__ __launch_bounds__(256) void natten_kernel(
    const float* __restrict__ qkv, float* __restrict__ out)
{
    extern __shared__ float sm[];
    float* Kt = sm;                       // 32 * 137
    float* Vs = Kt + 32 * KTS;            // 127 * 36
    float* Qs = Vs + 127 * RS;            // 64 * 36
    float* Pt = Qs + TQ * RS;             // 8 * 72 * 12

    const int t0 = blockIdx.x * TQ;
    const int h = blockIdx.y;
    const int tid = threadIdx.x;
    const int w = tid >> 5;
    const int lane = tid & 31;

    int base = t0 - 31;
    if (base < 0) base = 0;
    if (base > LSEQ - KV) base = LSEQ - KV;

    const float scale = 0.17677669529663687f;

    for (int idx = tid; idx < KV * 8; idx += 256) {
        int row = idx >> 3;
        int d4 = (idx & 7) * 4;
        size_t g = (size_t)(base + row) * C3 + CDIM + h * DH + d4;
        float4 kv = *(const float4*)&qkv[g];
        Kt[(d4 + 0) * KTS + row] = kv.x;
        Kt[(d4 + 1) * KTS + row] = kv.y;
        Kt[(d4 + 2) * KTS + row] = kv.z;
        Kt[(d4 + 3) * KTS + row] = kv.w;
        *(float4*)&Vs[row * RS + d4] = *(const float4*)&qkv[g + CDIM];
    }
    for (int idx = tid; idx < 32 * 11; idx += 256) {
        int d = idx & 31;
        int rr = 126 + (idx >> 5);
        Kt[d * KTS + rr] = 0.f;
    }
    if (tid < 32) Vs[126 * RS + tid] = 0.f;
    for (int idx = tid; idx < TQ * 8; idx += 256) {
        int row = idx >> 3;
        int d4 = (idx & 7) * 4;
        float4 q = *(const float4*)&qkv[(size_t)(t0 + row) * C3 + h * DH + d4];
        q.x *= scale; q.y *= scale; q.z *= scale; q.w *= scale;
        *(float4*)&Qs[row * RS + d4] = q;
    }
    __syncthreads();

    const int l0 = t0 + w * 8;
    const int ws0 = win_start(l0) - base;
    const int off7 = win_start(l0 + 7) - base - ws0;
    float* Ptw = Pt + w * PTROWS * PTS;
    const bool lk7 = (lane < 7);

    float s0[8], s1[8], s2[8];
    #pragma unroll
    for (int q = 0; q < 8; q++) { s0[q] = 0.f; s1[q] = 0.f; s2[q] = 0.f; }

    const float* qsw = &Qs[(w * 8) * RS];
    #pragma unroll 4
    for (int d = 0; d < 32; d++) {
        const float* ktd = &Kt[d * KTS + ws0 + lane];
        float k0 = ktd[0];
        float k1 = ktd[32];
        float k2 = lk7 ? ktd[64] : 0.f;
        #pragma unroll
        for (int q = 0; q < 8; q++) {
            float qd = qsw[q * RS + d];
            s0[q] = fmaf(qd, k0, s0[q]);
            s1[q] = fmaf(qd, k1, s1[q]);
            s2[q] = fmaf(qd, k2, s2[q]);
        }
    }

    #pragma unroll 1
    for (int q = 0; q < 8; q++) {
        const int off = win_start(l0 + q) - base - ws0;
        const bool v0 = (lane >= off);
        const bool v1 = (lane <= off + 30);
        const bool v2 = (lane + 2 <= off);
        float a0 = v0 ? s0[q] : -1e30f;
        float a1 = v1 ? s1[q] : -1e30f;
        float a2 = v2 ? s2[q] : -1e30f;
        float m = fmaxf(fmaxf(a0, a1), a2);
        #pragma unroll
        for (int o = 16; o > 0; o >>= 1)
            m = fmaxf(m, __shfl_xor_sync(0xffffffffu, m, o));
        float e0 = v0 ? __expf(s0[q] - m) : 0.f;
        float e1 = v1 ? __expf(s1[q] - m) : 0.f;
        float e2 = v2 ? __expf(s2[q] - m) : 0.f;
        float sum = e0 + e1 + e2;
        #pragma unroll
        for (int o = 16; o > 0; o >>= 1)
            sum += __shfl_xor_sync(0xffffffffu, sum, o);
        float inv = __frcp_rn(sum);
        Ptw[lane * PTS + q]        = e0 * inv;
        Ptw[(lane + 32) * PTS + q] = e1 * inv;
        if (lk7) Ptw[(lane + 64) * PTS + q] = e2 * inv;
    }
    __syncwarp();

    const int nU = off7 + 64;
    float acc[8];
    #pragma unroll
    for (int q = 0; q < 8; q++) acc[q] = 0.f;

    const float* vb = &Vs[ws0 * RS + lane];
    #pragma unroll 4
    for (int jj = 0; jj < nU; jj++) {
        float v = vb[jj * RS];
        float4 pa = *(const float4*)&Ptw[jj * PTS];
        float4 pb = *(const float4*)&Ptw[jj * PTS + 4];
        acc[0] = fmaf(pa.x, v, acc[0]);
        acc[1] = fmaf(pa.y, v, acc[1]);
        acc[2] = fmaf(pa.z, v, acc[2]);
        acc[3] = fmaf(pa.w, v, acc[3]);
        acc[4] = fmaf(pb.x, v, acc[4]);
        acc[5] = fmaf(pb.y, v, acc[5]);
        acc[6] = fmaf(pb.z, v, acc[6]);
        acc[7] = fmaf(pb.w, v, acc[7]);
    }

    // store k-permuted + rounded (GEMM3 PERM_A layout)
    const int plane = (lane & ~7) | (((lane & 3) << 1) | ((lane >> 2) & 1));
    #pragma unroll
    for (int q = 0; q < 8; q++)
        out[(size_t)(l0 + q) * CDIM + h * DH + plane] = round_tf32(acc[q]);
}

// ---------------------------------------------------------------------------
extern "C" void kernel_launch(void* const* d_in, const int* in_sizes, int n_in,
                              void* d_out, int out_size)
{
    const float* x    = (const float*)d_in[0];
    const float* Wp   = (const float*)d_in[1];
    const float* bp   = (const float*)d_in[2];
    const float* Wqkv = (const float*)d_in[3];
    const float* bqkv = (const float*)d_in[4];
    const float* Wo   = (const float*)d_in[5];
    const float* bo   = (const float*)d_in[6];
    float* out = (float*)d_out;

    float *p_y, *p_qkv, *p_att, *wpp, *wqp, *wop;
    cudaGetSymbolAddress((void**)&p_y,   g_y);
    cudaGetSymbolAddress((void**)&p_qkv, g_qkv);
    cudaGetSymbolAddress((void**)&p_att, g_att);
    cudaGetSymbolAddress((void**)&wpp, g_Wp_p);
    cudaGetSymbolAddress((void**)&wqp, g_Wq_p);
    cudaGetSymbolAddress((void**)&wop, g_Wo_p);

    const int natten_smem = (32 * KTS + 127 * RS + TQ * RS + 8 * PTROWS * PTS) * 4;
    static bool attr_set = false;
    if (!attr_set) {
        cudaFuncSetAttribute(natten_kernel,
                             cudaFuncAttributeMaxDynamicSharedMemorySize, natten_smem);
        attr_set = true;
    }

    prep_weights_kernel<<<(FIN * CDIM + 255) / 256, 256>>>(Wp, wpp, FIN, CDIM);
    prep_weights_kernel<<<(CDIM * C3 + 255) / 256, 256>>>(Wqkv, wqp, CDIM, C3);
    prep_weights_kernel<<<(CDIM * CDIM + 255) / 256, 256>>>(Wo, wop, CDIM, CDIM);

    // y = x @ Wp + bp : natural A + inline cvt; y stored k-permuted + rounded
    gemm_tf32_kernel<false, true><<<dim3(CDIM / 64, LSEQ / 128), 256>>>(
        x, wpp, bp, p_y, LSEQ, CDIM, FIN);

    // qkv = y @ Wqkv + bqkv : A = y (permuted, LDS.64 frags); out natural fp32
    gemm_tf32_kernel<true, false><<<dim3(C3 / 64, LSEQ / 128), 256>>>(
        p_y, wqp, bqkv, p_qkv, LSEQ, C3, CDIM);

    natten_kernel<<<dim3(LSEQ / TQ, NH), 256, natten_smem>>>(p_qkv, p_att);

    // out = att @ Wo + bo : A = att (permuted); out natural fp32
    gemm_tf32_kernel<true, false><<<dim3(CDIM / 64, LSEQ / 128), 256>>>(
        p_att, wop, bo, out, LSEQ, CDIM, CDIM);
}

// round 17
// speedup vs baseline: 1.2672x; 1.0087x over previous
#include <cuda_runtime.h>
#include <cuda_bf16.h>
#include <cstdint>

#define LSEQ 8192
#define FIN  1024
#define CDIM 256
#define C3   768
#define NH   8
#define DH   32
#define KS   63

__device__ float g_y[LSEQ * CDIM];     // k-permuted + rounded (GEMM2 A)
__device__ float g_qkv[LSEQ * C3];     // natural fp32
__device__ float g_att[LSEQ * CDIM];   // k-permuted + rounded (GEMM3 A)

// Fragment-permuted tf32-rounded weights (round-12 layout)
__device__ float g_Wp_p[(FIN / 8) * (CDIM / 8) * 64];
__device__ float g_Wq_p[(CDIM / 8) * (C3 / 8) * 64];
__device__ float g_Wo_p[(CDIM / 8) * (CDIM / 8) * 64];

// ---------------------------------------------------------------------------
// helpers
// ---------------------------------------------------------------------------
__device__ __forceinline__ void cp16(void* smem, const void* g) {
    uint32_t s = (uint32_t)__cvta_generic_to_shared(smem);
    asm volatile("cp.async.cg.shared.global [%0], [%1], 16;\n" :: "r"(s), "l"(g));
}
__device__ __forceinline__ void cp_commit() {
    asm volatile("cp.async.commit_group;\n");
}
__device__ __forceinline__ void mma_tf32(float* d, const uint32_t* a, const uint32_t* b) {
    asm volatile(
        "mma.sync.aligned.m16n8k8.row.col.f32.tf32.tf32.f32 "
        "{%0,%1,%2,%3}, {%4,%5,%6,%7}, {%8,%9}, {%0,%1,%2,%3};\n"
        : "+f"(d[0]), "+f"(d[1]), "+f"(d[2]), "+f"(d[3])
        : "r"(a[0]), "r"(a[1]), "r"(a[2]), "r"(a[3]), "r"(b[0]), "r"(b[1]));
}
__device__ __forceinline__ uint32_t cvt_rna_tf32(float x) {
    uint32_t r;
    asm("cvt.rna.tf32.f32 %0, %1;" : "=r"(r) : "f"(x));
    return r;
}
__device__ __forceinline__ float round_tf32(float x) {
    return __uint_as_float(cvt_rna_tf32(x));
}
// k-chunk permutation (low 3 bits): logical j -> physical ((j&3)<<1)|(j>>2)
__device__ __forceinline__ int permc(int k) {
    return (k & ~7) | (((k & 3) << 1) | ((k >> 2) & 1));
}

// ---------------------------------------------------------------------------
// Prep: W[K][N] -> Bp fragment-permuted, tf32-RNE rounded (round-12 layout)
// ---------------------------------------------------------------------------
__global__ void prep_weights_kernel(const float* __restrict__ W,
                                    float* __restrict__ Bp, int K, int N)
{
    int idx = blockIdx.x * blockDim.x + threadIdx.x;
    int total = (K / 8) * (N / 8) * 64;
    if (idx >= total) return;
    int slot = idx & 1;
    int lane = (idx >> 1) & 31;
    int blk  = idx >> 6;
    int n8   = blk % (N / 8);
    int k8   = blk / (N / 8);
    int kk = k8 * 8 + slot * 4 + (lane & 3);
    int nn = n8 * 8 + (lane >> 2);
    Bp[idx] = round_tf32(W[(size_t)kk * N + nn]);
}

// ---------------------------------------------------------------------------
// TF32 GEMM: BM=128 BN=64 BK=16, 2-stage, B fragment-permuted.
// PERM_A: A k-permuted -> paired LDS.64 frag loads (AST=24, conflict-free).
// else:   natural A, scalar LDS + inline cvt.rna (AST=20, conflict-free).
// PERM_OUT: store C k-permuted + tf32-rounded (feeds a PERM_A GEMM).
// ---------------------------------------------------------------------------
template<bool PERM_A, bool PERM_OUT, int AST>
__global__ __launch_bounds__(256) void gemm_tf32_kernel(
    const float* __restrict__ A, const float* __restrict__ Bp,
    const float* __restrict__ bias, float* __restrict__ C,
    int M, int N, int K)
{
    __shared__ float As[2][128 * AST];
    __shared__ float Bs[2][1024];

    const int bm = blockIdx.y * 128;
    const int bn = blockIdx.x * 64;
    const int tid = threadIdx.x;
    const int wid = tid >> 5;
    const int lane = tid & 31;
    const int warp_m = wid & 3;
    const int warp_n = wid >> 2;
    const int r = lane >> 2;
    const int c = lane & 3;

    const int arow0 = tid >> 2;
    const int ac4   = (tid & 3) * 4;
    const int bk8l  = tid >> 7;
    const int bn8l  = (tid >> 4) & 7;
    const int bpart = tid & 15;
    const int n8cnt = N >> 3;

    float acc[2][4][4];
    #pragma unroll
    for (int i = 0; i < 2; i++)
        #pragma unroll
        for (int j = 0; j < 4; j++)
            #pragma unroll
            for (int e = 0; e < 4; e++) acc[i][j][e] = 0.f;

    const int T = K >> 4;

    auto stage = [&](int kt, int s) {
        const int k0 = kt << 4;
        cp16(&As[s][arow0 * AST + ac4], &A[(size_t)(bm + arow0) * K + k0 + ac4]);
        cp16(&As[s][(arow0 + 64) * AST + ac4], &A[(size_t)(bm + arow0 + 64) * K + k0 + ac4]);
        cp16(&Bs[s][(bk8l * 8 + bn8l) * 64 + bpart * 4],
             &Bp[(size_t)(((k0 >> 3) + bk8l) * n8cnt + (bn >> 3) + bn8l) * 64 + bpart * 4]);
        cp_commit();
    };

    stage(0, 0);

    for (int kt = 0; kt < T; kt++) {
        const int buf = kt & 1;
        if (kt + 1 < T) {
            stage(kt + 1, buf ^ 1);
            asm volatile("cp.async.wait_group 1;\n");
        } else {
            asm volatile("cp.async.wait_group 0;\n");
        }
        __syncthreads();

        const float* as = As[buf];
        const float* bs = Bs[buf];
        #pragma unroll
        for (int ks = 0; ks < 16; ks += 8) {
            uint32_t af[2][4], bf[4][2];
            #pragma unroll
            for (int mi = 0; mi < 2; mi++) {
                int m0 = warp_m * 32 + mi * 16;
                if (PERM_A) {
                    float2 pA = *(const float2*)&as[(m0 + r)     * AST + ks + 2 * c];
                    float2 pB = *(const float2*)&as[(m0 + r + 8) * AST + ks + 2 * c];
                    af[mi][0] = __float_as_uint(pA.x);
                    af[mi][1] = __float_as_uint(pB.x);
                    af[mi][2] = __float_as_uint(pA.y);
                    af[mi][3] = __float_as_uint(pB.y);
                } else {
                    af[mi][0] = cvt_rna_tf32(as[(m0 + r)     * AST + ks + c]);
                    af[mi][1] = cvt_rna_tf32(as[(m0 + r + 8) * AST + ks + c]);
                    af[mi][2] = cvt_rna_tf32(as[(m0 + r)     * AST + ks + c + 4]);
                    af[mi][3] = cvt_rna_tf32(as[(m0 + r + 8) * AST + ks + c + 4]);
                }
            }
            const int k8l = ks >> 3;
            #pragma unroll
            for (int nj = 0; nj < 4; nj++) {
                const float2 bb = *(const float2*)&bs[(k8l * 8 + warp_n * 4 + nj) * 64 + lane * 2];
                bf[nj][0] = __float_as_uint(bb.x);
                bf[nj][1] = __float_as_uint(bb.y);
            }
            #pragma unroll
            for (int mi = 0; mi < 2; mi++)
                #pragma unroll
                for (int nj = 0; nj < 4; nj++)
                    mma_tf32(acc[mi][nj], af[mi], bf[nj]);
        }
        __syncthreads();
    }

    #pragma unroll
    for (int mi = 0; mi < 2; mi++) {
        #pragma unroll
        for (int nj = 0; nj < 4; nj++) {
            int row = bm + warp_m * 32 + mi * 16 + r;
            int col = bn + warp_n * 32 + nj * 8 + c * 2;
            float2 bb = *(const float2*)&bias[col];
            float v00 = acc[mi][nj][0] + bb.x;
            float v01 = acc[mi][nj][1] + bb.y;
            float v10 = acc[mi][nj][2] + bb.x;
            float v11 = acc[mi][nj][3] + bb.y;
            if (PERM_OUT) {
                int p0 = permc(col);
                int p1 = permc(col + 1);
                C[(size_t)row * N + p0]       = round_tf32(v00);
                C[(size_t)row * N + p1]       = round_tf32(v01);
                C[(size_t)(row + 8) * N + p0] = round_tf32(v10);
                C[(size_t)(row + 8) * N + p1] = round_tf32(v11);
            } else {
                *(float2*)&C[(size_t)row * N + col]       = make_float2(v00, v01);
                *(float2*)&C[(size_t)(row + 8) * N + col] = make_float2(v10, v11);
            }
        }
    }
}

// ---------------------------------------------------------------------------
// NATTEN-1D v3 (round-14): transposed-K outer product.
// att stored k-permuted + tf32-rounded (GEMM3 PERM_A layout).
// ---------------------------------------------------------------------------
#define TQ 64
#define KV 126
#define RS 36
#define KTS 137
#define PTS 12
#define PTROWS 72

__device__ __forceinline__ int win_start(int l) {
    int s = l - 31;
    if (s < 0) s = 0;
    if (s > LSEQ - KS) s = LSEQ - KS;
    return s;
}

__global__ __launch_bounds__(256) void natten_kernel(
    const float* __restrict__ qkv, float* __restrict__ out)
{
    extern __shared__ float sm[];
    float* Kt = sm;                       // 32 * 137
    float* Vs = Kt + 32 * KTS;            // 127 * 36
    float* Qs = Vs + 127 * RS;            // 64 * 36
    float* Pt = Qs + TQ * RS;             // 8 * 72 * 12

    const int t0 = blockIdx.x * TQ;
    const int h = blockIdx.y;
    const int tid = threadIdx.x;
    const int w = tid >> 5;
    const int lane = tid & 31;

    int base = t0 - 31;
    if (base < 0) base = 0;
    if (base > LSEQ - KV) base = LSEQ - KV;

    const float scale = 0.17677669529663687f;

    for (int idx = tid; idx < KV * 8; idx += 256) {
        int row = idx >> 3;
        int d4 = (idx & 7) * 4;
        size_t g = (size_t)(base + row) * C3 + CDIM + h * DH + d4;
        float4 kv = *(const float4*)&qkv[g];
        Kt[(d4 + 0) * KTS + row] = kv.x;
        Kt[(d4 + 1) * KTS + row] = kv.y;
        Kt[(d4 + 2) * KTS + row] = kv.z;
        Kt[(d4 + 3) * KTS + row] = kv.w;
        *(float4*)&Vs[row * RS + d4] = *(const float4*)&qkv[g + CDIM];
    }
    for (int idx = tid; idx < 32 * 11; idx += 256) {
        int d = idx & 31;
        int rr = 126 + (idx >> 5);
        Kt[d * KTS + rr] = 0.f;
    }
    if (tid < 32) Vs[126 * RS + tid] = 0.f;
    for (int idx = tid; idx < TQ * 8; idx += 256) {
        int row = idx >> 3;
        int d4 = (idx & 7) * 4;
        float4 q = *(const float4*)&qkv[(size_t)(t0 + row) * C3 + h * DH + d4];
        q.x *= scale; q.y *= scale; q.z *= scale; q.w *= scale;
        *(float4*)&Qs[row * RS + d4] = q;
    }
    __syncthreads();

    const int l0 = t0 + w * 8;
    const int ws0 = win_start(l0) - base;
    const int off7 = win_start(l0 + 7) - base - ws0;
    float* Ptw = Pt + w * PTROWS * PTS;
    const bool lk7 = (lane < 7);

    float s0[8], s1[8], s2[8];
    #pragma unroll
    for (int q = 0; q < 8; q++) { s0[q] = 0.f; s1[q] = 0.f; s2[q] = 0.f; }

    const float* qsw = &Qs[(w * 8) * RS];
    #pragma unroll 4
    for (int d = 0; d < 32; d++) {
        const float* ktd = &Kt[d * KTS + ws0 + lane];
        float k0 = ktd[0];
        float k1 = ktd[32];
        float k2 = lk7 ? ktd[64] : 0.f;
        #pragma unroll
        for (int q = 0; q < 8; q++) {
            float qd = qsw[q * RS + d];
            s0[q] = fmaf(qd, k0, s0[q]);
            s1[q] = fmaf(qd, k1, s1[q]);
            s2[q] = fmaf(qd, k2, s2[q]);
        }
    }

    #pragma unroll 1
    for (int q = 0; q < 8; q++) {
        const int off = win_start(l0 + q) - base - ws0;
        const bool v0 = (lane >= off);
        const bool v1 = (lane <= off + 30);
        const bool v2 = (lane + 2 <= off);
        float a0 = v0 ? s0[q] : -1e30f;
        float a1 = v1 ? s1[q] : -1e30f;
        float a2 = v2 ? s2[q] : -1e30f;
        float m = fmaxf(fmaxf(a0, a1), a2);
        #pragma unroll
        for (int o = 16; o > 0; o >>= 1)
            m = fmaxf(m, __shfl_xor_sync(0xffffffffu, m, o));
        float e0 = v0 ? __expf(s0[q] - m) : 0.f;
        float e1 = v1 ? __expf(s1[q] - m) : 0.f;
        float e2 = v2 ? __expf(s2[q] - m) : 0.f;
        float sum = e0 + e1 + e2;
        #pragma unroll
        for (int o = 16; o > 0; o >>= 1)
            sum += __shfl_xor_sync(0xffffffffu, sum, o);
        float inv = __frcp_rn(sum);
        Ptw[lane * PTS + q]        = e0 * inv;
        Ptw[(lane + 32) * PTS + q] = e1 * inv;
        if (lk7) Ptw[(lane + 64) * PTS + q] = e2 * inv;
    }
    __syncwarp();

    const int nU = off7 + 64;
    float acc[8];
    #pragma unroll
    for (int q = 0; q < 8; q++) acc[q] = 0.f;

    const float* vb = &Vs[ws0 * RS + lane];
    #pragma unroll 4
    for (int jj = 0; jj < nU; jj++) {
        float v = vb[jj * RS];
        float4 pa = *(const float4*)&Ptw[jj * PTS];
        float4 pb = *(const float4*)&Ptw[jj * PTS + 4];
        acc[0] = fmaf(pa.x, v, acc[0]);
        acc[1] = fmaf(pa.y, v, acc[1]);
        acc[2] = fmaf(pa.z, v, acc[2]);
        acc[3] = fmaf(pa.w, v, acc[3]);
        acc[4] = fmaf(pb.x, v, acc[4]);
        acc[5] = fmaf(pb.y, v, acc[5]);
        acc[6] = fmaf(pb.z, v, acc[6]);
        acc[7] = fmaf(pb.w, v, acc[7]);
    }

    // store k-permuted + rounded (GEMM3 PERM_A layout)
    const int plane = (lane & ~7) | (((lane & 3) << 1) | ((lane >> 2) & 1));
    #pragma unroll
    for (int q = 0; q < 8; q++)
        out[(size_t)(l0 + q) * CDIM + h * DH + plane] = round_tf32(acc[q]);
}

// ---------------------------------------------------------------------------
extern "C" void kernel_launch(void* const* d_in, const int* in_sizes, int n_in,
                              void* d_out, int out_size)
{
    const float* x    = (const float*)d_in[0];
    const float* Wp   = (const float*)d_in[1];
    const float* bp   = (const float*)d_in[2];
    const float* Wqkv = (const float*)d_in[3];
    const float* bqkv = (const float*)d_in[4];
    const float* Wo   = (const float*)d_in[5];
    const float* bo   = (const float*)d_in[6];
    float* out = (float*)d_out;

    float *p_y, *p_qkv, *p_att, *wpp, *wqp, *wop;
    cudaGetSymbolAddress((void**)&p_y,   g_y);
    cudaGetSymbolAddress((void**)&p_qkv, g_qkv);
    cudaGetSymbolAddress((void**)&p_att, g_att);
    cudaGetSymbolAddress((void**)&wpp, g_Wp_p);
    cudaGetSymbolAddress((void**)&wqp, g_Wq_p);
    cudaGetSymbolAddress((void**)&wop, g_Wo_p);

    const int natten_smem = (32 * KTS + 127 * RS + TQ * RS + 8 * PTROWS * PTS) * 4;
    static bool attr_set = false;
    if (!attr_set) {
        cudaFuncSetAttribute(natten_kernel,
                             cudaFuncAttributeMaxDynamicSharedMemorySize, natten_smem);
        attr_set = true;
    }

    prep_weights_kernel<<<(FIN * CDIM + 255) / 256, 256>>>(Wp, wpp, FIN, CDIM);
    prep_weights_kernel<<<(CDIM * C3 + 255) / 256, 256>>>(Wqkv, wqp, CDIM, C3);
    prep_weights_kernel<<<(CDIM * CDIM + 255) / 256, 256>>>(Wo, wop, CDIM, CDIM);

    // y = x @ Wp + bp : natural A (AST=20) + inline cvt; y stored k-permuted
    gemm_tf32_kernel<false, true, 20><<<dim3(CDIM / 64, LSEQ / 128), 256>>>(
        x, wpp, bp, p_y, LSEQ, CDIM, FIN);

    // qkv = y @ Wqkv + bqkv : A = y permuted (AST=24, LDS.64); out natural
    gemm_tf32_kernel<true, false, 24><<<dim3(C3 / 64, LSEQ / 128), 256>>>(
        p_y, wqp, bqkv, p_qkv, LSEQ, C3, CDIM);

    natten_kernel<<<dim3(LSEQ / TQ, NH), 256, natten_smem>>>(p_qkv, p_att);

    // out = att @ Wo + bo : A = att permuted (AST=24); out natural
    gemm_tf32_kernel<true, false, 24><<<dim3(CDIM / 64, LSEQ / 128), 256>>>(
        p_att, wop, bo, out, LSEQ, CDIM, CDIM);
}